// round 12
// baseline (speedup 1.0000x reference)
#include <cuda_runtime.h>
#include <cuda_fp16.h>
#include <cuda_bf16.h>

// Problem constants (from reference_code)
#define N_PATHS  10000000
#define MAX_LEN  3
#define N_NODES  100000
#define HIDDEN   128

// fp16 planar projection table: g_t16[l * N_NODES + node], 600 KB total.
__device__ __half g_t16[3 * N_NODES];

// ---------------------------------------------------------------------------
// Kernel 1: proj[l][node] = dot(feature[node], W[l][0]) -> fp16 planar table.
// FOUR lanes per node (8 nodes per warp): each lane accumulates 32 dims
// sequentially in fp32, then a 2-level shuffle tree finishes the dot.
// SHFL count: 6 per node (vs 15 for warp-wide tree) -> shuffle-unit pressure
// drops ~2.5x; kernel becomes DRAM-bound (~8 us for 51.2 MB).
// W (1.5 KB) stays L1-resident; every W load is a 1-line broadcast.
// ---------------------------------------------------------------------------
__global__ void __launch_bounds__(256)
proj_kernel(const float* __restrict__ nf, const float* __restrict__ W) {
    const int lane   = threadIdx.x & 31;
    const int sub    = lane & 3;    // float4 slot within the node's 64B chunk
    const int nin    = lane >> 2;   // node within warp (0..7)
    const int warpId = (blockIdx.x * blockDim.x + threadIdx.x) >> 5;
    const int node   = warpId * 8 + nin;
    if (node >= N_NODES) return;

    const float4* nf4 = ((const float4*)nf) + (size_t)node * 32 + sub;
    const float4* w4  = (const float4*)W;

    float s0 = 0.0f, s1 = 0.0f, s2 = 0.0f;
    #pragma unroll
    for (int k = 0; k < 8; k++) {
        const float4 f = __ldcs(nf4 + 4 * k);              // streaming nf read
        const float4 a = __ldg(w4 + 0  + sub + 4 * k);     // L1-resident W
        const float4 b = __ldg(w4 + 32 + sub + 4 * k);
        const float4 c = __ldg(w4 + 64 + sub + 4 * k);
        s0 += f.x * a.x + f.y * a.y + f.z * a.z + f.w * a.w;
        s1 += f.x * b.x + f.y * b.y + f.z * b.z + f.w * b.w;
        s2 += f.x * c.x + f.y * c.y + f.z * c.z + f.w * c.w;
    }

    // 2-level reduction within each aligned 4-lane group
    s0 += __shfl_xor_sync(0xFFFFFFFFu, s0, 1);
    s1 += __shfl_xor_sync(0xFFFFFFFFu, s1, 1);
    s2 += __shfl_xor_sync(0xFFFFFFFFu, s2, 1);
    s0 += __shfl_xor_sync(0xFFFFFFFFu, s0, 2);
    s1 += __shfl_xor_sync(0xFFFFFFFFu, s1, 2);
    s2 += __shfl_xor_sync(0xFFFFFFFFu, s2, 2);

    if (sub == 0) {
        g_t16[0 * N_NODES + node] = __float2half(s0);
        g_t16[1 * N_NODES + node] = __float2half(s1);
        g_t16[2 * N_NODES + node] = __float2half(s2);
    }
}

// ---------------------------------------------------------------------------
// Kernel 2: gather + masked mean. BYTE-IDENTICAL to R7 (measured at the
// L1tex wavefront floor, ~101 us across three runs; protected).
// ---------------------------------------------------------------------------
__global__ void __launch_bounds__(256)
gather_kernel(const int* __restrict__ paths, float* __restrict__ out) {
    const long long tid = (long long)blockIdx.x * blockDim.x + threadIdx.x;
    if (tid >= (N_PATHS / 4)) return;

    const int4* p4 = ((const int4*)paths) + tid * 3;
    int4 v0 = __ldcs(p4 + 0);
    int4 v1 = __ldcs(p4 + 1);
    int4 v2 = __ldcs(p4 + 2);

    int idx[12] = { v0.x, v0.y, v0.z, v0.w,
                    v1.x, v1.y, v1.z, v1.w,
                    v2.x, v2.y, v2.z, v2.w };

    float4 res;
    float* r = (float*)&res;

    #pragma unroll
    for (int k = 0; k < 4; k++) {
        float s = 0.0f;
        int   cnt = 0;
        #pragma unroll
        for (int l = 0; l < 3; l++) {
            const int p = idx[k * 3 + l];
            if (p >= 0) {                     // predicated LDG + SEL (no branch)
                s += __half2float(g_t16[l * N_NODES + p]);
                cnt++;
            }
        }
        float inv = (cnt == 3) ? (1.0f / 3.0f)
                               : ((cnt == 2) ? 0.5f : 1.0f);
        r[k] = s * inv;
    }

    __stcs(((float4*)out) + tid, res);
}

// ---------------------------------------------------------------------------
// Launch. Inputs identified by element count:
//   30,000,000 -> paths (int32 [10M,3]); 12,800,000 -> node_feature; 384 -> W
// ---------------------------------------------------------------------------
extern "C" void kernel_launch(void* const* d_in, const int* in_sizes, int n_in,
                              void* d_out, int out_size) {
    const void*  paths_raw = nullptr;
    const float* nf        = nullptr;
    const float* W         = nullptr;

    for (int i = 0; i < n_in; i++) {
        if      (in_sizes[i] == N_PATHS * MAX_LEN)  paths_raw = d_in[i];
        else if (in_sizes[i] == N_NODES * HIDDEN)   nf        = (const float*)d_in[i];
        else if (in_sizes[i] == MAX_LEN * HIDDEN)   W         = (const float*)d_in[i];
    }

    float* out = (float*)d_out;

    // proj: 8 nodes per warp -> 12500 warps -> 400000 threads -> 1563 blocks
    {
        const int threads = 256;
        const int warps   = (N_NODES + 7) / 8;            // 12500
        const int blocks  = (warps * 32 + threads - 1) / threads;
        proj_kernel<<<blocks, threads>>>(nf, W);
    }

    // gather: 2.5M threads, 4 paths each (R7-proven launch shape)
    {
        const int threads = 256;
        const long long nThreads = N_PATHS / 4;
        const int blocks = (int)((nThreads + threads - 1) / threads);
        gather_kernel<<<blocks, threads>>>((const int*)paths_raw, out);
    }
}

// round 13
// speedup vs baseline: 1.0419x; 1.0419x over previous
#include <cuda_runtime.h>
#include <cuda_fp16.h>
#include <cuda_bf16.h>

// Problem constants (from reference_code)
#define N_PATHS  10000000
#define MAX_LEN  3
#define N_NODES  100000
#define HIDDEN   128

// fp16 planar projection table: g_t16[l * N_NODES + node], 600 KB total.
__device__ __half g_t16[3 * N_NODES];

// ---------------------------------------------------------------------------
// Kernel 1: proj[l][node] = dot(feature[node], W[l][0]) -> fp16 planar table.
// R12 body (4 lanes/node, 8 nodes/warp, 2-level shuffle reduce). DRAM-bound.
// ---------------------------------------------------------------------------
__global__ void __launch_bounds__(256)
proj_kernel(const float* __restrict__ nf, const float* __restrict__ W) {
    const int lane   = threadIdx.x & 31;
    const int sub    = lane & 3;
    const int nin    = lane >> 2;
    const int warpId = (blockIdx.x * blockDim.x + threadIdx.x) >> 5;
    const int node   = warpId * 8 + nin;
    if (node >= N_NODES) return;

    const float4* nf4 = ((const float4*)nf) + (size_t)node * 32 + sub;
    const float4* w4  = (const float4*)W;

    float s0 = 0.0f, s1 = 0.0f, s2 = 0.0f;
    #pragma unroll
    for (int k = 0; k < 8; k++) {
        const float4 f = __ldcs(nf4 + 4 * k);
        const float4 a = __ldg(w4 + 0  + sub + 4 * k);
        const float4 b = __ldg(w4 + 32 + sub + 4 * k);
        const float4 c = __ldg(w4 + 64 + sub + 4 * k);
        s0 += f.x * a.x + f.y * a.y + f.z * a.z + f.w * a.w;
        s1 += f.x * b.x + f.y * b.y + f.z * b.z + f.w * b.w;
        s2 += f.x * c.x + f.y * c.y + f.z * c.z + f.w * c.w;
    }

    s0 += __shfl_xor_sync(0xFFFFFFFFu, s0, 1);
    s1 += __shfl_xor_sync(0xFFFFFFFFu, s1, 1);
    s2 += __shfl_xor_sync(0xFFFFFFFFu, s2, 1);
    s0 += __shfl_xor_sync(0xFFFFFFFFu, s0, 2);
    s1 += __shfl_xor_sync(0xFFFFFFFFu, s1, 2);
    s2 += __shfl_xor_sync(0xFFFFFFFFu, s2, 2);

    if (sub == 0) {
        g_t16[0 * N_NODES + node] = __float2half(s0);
        g_t16[1 * N_NODES + node] = __float2half(s1);
        g_t16[2 * N_NODES + node] = __float2half(s2);
    }
}

// ---------------------------------------------------------------------------
// Kernel 2: gather + masked mean, launched with PDL. Paths are loaded BEFORE
// cudaGridDependencySynchronize() (they don't depend on proj), so gather
// launch ramp + the 120 MB paths stream overlap proj execution. Table
// gathers (the protected R7 loop) run after the dependency resolves.
// ---------------------------------------------------------------------------
__global__ void __launch_bounds__(256)
gather_kernel(const int* __restrict__ paths, float* __restrict__ out) {
    const long long tid = (long long)blockIdx.x * blockDim.x + threadIdx.x;
    if (tid >= (N_PATHS / 4)) return;

    // Pre-dependency work: stream in this thread's 4 paths (48 B)
    const int4* p4 = ((const int4*)paths) + tid * 3;
    int4 v0 = __ldcs(p4 + 0);
    int4 v1 = __ldcs(p4 + 1);
    int4 v2 = __ldcs(p4 + 2);

    // Wait for proj_kernel completion (PDL); table stores are visible after.
    cudaGridDependencySynchronize();

    int idx[12] = { v0.x, v0.y, v0.z, v0.w,
                    v1.x, v1.y, v1.z, v1.w,
                    v2.x, v2.y, v2.z, v2.w };

    float4 res;
    float* r = (float*)&res;

    #pragma unroll
    for (int k = 0; k < 4; k++) {
        float s = 0.0f;
        int   cnt = 0;
        #pragma unroll
        for (int l = 0; l < 3; l++) {
            const int p = idx[k * 3 + l];
            if (p >= 0) {                     // predicated LDG + SEL (no branch)
                s += __half2float(g_t16[l * N_NODES + p]);
                cnt++;
            }
        }
        float inv = (cnt == 3) ? (1.0f / 3.0f)
                               : ((cnt == 2) ? 0.5f : 1.0f);
        r[k] = s * inv;
    }

    __stcs(((float4*)out) + tid, res);
}

// ---------------------------------------------------------------------------
// Launch. Inputs identified by element count:
//   30,000,000 -> paths (int32 [10M,3]); 12,800,000 -> node_feature; 384 -> W
// gather is launched with ProgrammaticStreamSerialization so it overlaps
// proj; correctness is preserved by cudaGridDependencySynchronize() in-kernel.
// ---------------------------------------------------------------------------
extern "C" void kernel_launch(void* const* d_in, const int* in_sizes, int n_in,
                              void* d_out, int out_size) {
    const void*  paths_raw = nullptr;
    const float* nf        = nullptr;
    const float* W         = nullptr;

    for (int i = 0; i < n_in; i++) {
        if      (in_sizes[i] == N_PATHS * MAX_LEN)  paths_raw = d_in[i];
        else if (in_sizes[i] == N_NODES * HIDDEN)   nf        = (const float*)d_in[i];
        else if (in_sizes[i] == MAX_LEN * HIDDEN)   W         = (const float*)d_in[i];
    }

    float* out = (float*)d_out;

    // proj: 8 nodes per warp -> 12500 warps -> 1563 blocks of 256
    {
        const int threads = 256;
        const int warps   = (N_NODES + 7) / 8;
        const int blocks  = (warps * 32 + threads - 1) / threads;
        proj_kernel<<<blocks, threads>>>(nf, W);
    }

    // gather with PDL: overlaps proj; in-kernel dependency sync guards table
    {
        const int threads = 256;
        const long long nThreads = N_PATHS / 4;
        const int blocks = (int)((nThreads + threads - 1) / threads);

        cudaLaunchAttribute attrs[1];
        attrs[0].id = cudaLaunchAttributeProgrammaticStreamSerialization;
        attrs[0].val.programmaticStreamSerializationAllowed = 1;

        cudaLaunchConfig_t cfg = {};
        cfg.gridDim  = dim3((unsigned)blocks, 1, 1);
        cfg.blockDim = dim3((unsigned)threads, 1, 1);
        cfg.dynamicSmemBytes = 0;
        cfg.stream   = 0;              // capture/default stream
        cfg.attrs    = attrs;
        cfg.numAttrs = 1;

        cudaLaunchKernelEx(&cfg, gather_kernel,
                           (const int*)paths_raw, out);
    }
}